// round 6
// baseline (speedup 1.0000x reference)
#include <cuda_runtime.h>
#include <math.h>

// ---------------------------------------------------------------------------
// DenseCRF mean-field with permutohedral lattice filtering.
// Padded float4 rows (21->24 ch), fused update+splat, merged bi/sp launches,
// triple-buffered so zeroing rides inside blur pass 0, 2-rows-per-thread blur.
// ---------------------------------------------------------------------------

#define CC 21
#define GRP 6                       // float4 groups per padded row (24 floats)
static constexpr int       NPIX    = 512 * 512;
static constexpr long long ROWS_BI = 6LL * NPIX + 1;   // worst-case rows
static constexpr long long ROWS_SP = 3LL * NPIX + 1;

// Scratch (device globals; allocated at module load, not at runtime).
__device__ float4 g_bi_a[ROWS_BI * GRP];
__device__ float4 g_bi_b[ROWS_BI * GRP];
__device__ float4 g_bi_c[ROWS_BI * GRP];
__device__ float4 g_sp_a[ROWS_SP * GRP];
__device__ float4 g_sp_b[ROWS_SP * GRP];
__device__ float4 g_sp_c[ROWS_SP * GRP];
__device__ float  g_nbi[NPIX];
__device__ float  g_nsp[NPIX];

__device__ __forceinline__ float4* valptr4(int id) {
    switch (id) {
        case 0:  return g_bi_a;
        case 1:  return g_bi_b;
        case 2:  return g_bi_c;
        case 3:  return g_sp_a;
        case 4:  return g_sp_b;
        default: return g_sp_c;
    }
}

__device__ __forceinline__ void red_add_v4(float4* p, float a, float b, float c, float d) {
    asm volatile("red.global.add.v4.f32 [%0], {%1, %2, %3, %4};"
                 :: "l"(p), "f"(a), "f"(b), "f"(c), "f"(d) : "memory");
}

// ---------------------------------------------------------------------------

// zero the 1-channel fronts of two buffers (float counts)
__global__ __launch_bounds__(256) void k_zero_fronts(int ida, long long na,
                                                     int idb, long long nb) {
    long long i = (long long)blockIdx.x * blockDim.x + threadIdx.x;
    if (i >= na + nb) return;
    if (i < na) ((float*)valptr4(ida))[i]      = 0.0f;
    else        ((float*)valptr4(idb))[i - na] = 0.0f;
}

// 1-channel splat for both lattices + zero two full 24-ch buffers (float4 counts)
__global__ __launch_bounds__(256) void k_splat1z(const float* __restrict__ ws_bi,
                                                 const int* __restrict__ os_bi, int N6,
                                                 const float* __restrict__ ws_sp,
                                                 const int* __restrict__ os_sp, int N3,
                                                 int za, long long zna,
                                                 int zb, long long znb) {
    long long i = (long long)blockIdx.x * blockDim.x + threadIdx.x;
    if (i < N6) { atomicAdd((float*)valptr4(0) + os_bi[i], ws_bi[i]); return; }
    if (i < N6 + N3) { long long j = i - N6; atomicAdd((float*)valptr4(3) + os_sp[j], ws_sp[j]); return; }
    long long z = i - (N6 + N3);
    if (z < zna)            valptr4(za)[z]       = make_float4(0.f, 0.f, 0.f, 0.f);
    else if (z < zna + znb) valptr4(zb)[z - zna] = make_float4(0.f, 0.f, 0.f, 0.f);
}

__global__ __launch_bounds__(256) void k_blur1_both(int bd, int bs,
                                                    const int* __restrict__ nbr_b, int Mb,
                                                    int sd, int ss,
                                                    const int* __restrict__ nbr_s, int Ms,
                                                    int hassp) {
    int nb = Mb + 1;
    int ns = hassp ? (Ms + 1) : 0;
    int i = blockIdx.x * blockDim.x + threadIdx.x;
    if (i >= nb + ns) return;
    int did, sid; const int* nbr; int r;
    if (i < nb) { did = bd; sid = bs; nbr = nbr_b; r = i; }
    else        { did = sd; sid = ss; nbr = nbr_s; r = i - nb; }
    float*       dst = (float*)valptr4(did);
    const float* src = (const float*)valptr4(sid);
    if (r == 0) { dst[0] = 0.0f; return; }
    int2 nn = ((const int2*)nbr)[r - 1];
    dst[r] = src[r] + 0.5f * (src[nn.x] + src[nn.y]);
}

__global__ __launch_bounds__(256) void k_norm_both(int bvid, int svid,
                                                   const float* __restrict__ ws_bi,
                                                   const int* __restrict__ os_bi,
                                                   const float* __restrict__ ws_sp,
                                                   const int* __restrict__ os_sp,
                                                   int N, float a_bi, float a_sp) {
    int n = blockIdx.x * blockDim.x + threadIdx.x;
    if (n >= N) return;
    const float* vb = (const float*)valptr4(bvid);
    float s = 0.0f;
#pragma unroll
    for (int j = 0; j < 6; j++) s += ws_bi[n * 6 + j] * vb[os_bi[n * 6 + j]];
    g_nbi[n] = 1.0f / (sqrtf(a_bi * s) + 1e-20f);
    const float* vs = (const float*)valptr4(svid);
    float t = 0.0f;
#pragma unroll
    for (int j = 0; j < 3; j++) t += ws_sp[n * 3 + j] * vs[os_sp[n * 3 + j]];
    g_nsp[n] = 1.0f / (sqrtf(a_sp * t) + 1e-20f);
}

// ---- 24-ch blur, bi+sp merged, 2 rows per thread, optional zero ranges ----

__global__ __launch_bounds__(256) void k_blur4z(int bd, int bs,
                                                const int* __restrict__ nbr_b, int Mb,
                                                int sd, int ss,
                                                const int* __restrict__ nbr_s, int Ms,
                                                int hassp,
                                                int za, long long zna,
                                                int zb, long long znb) {
    long long nbt = (long long)((Mb + 2) / 2) * GRP;               // bi thread count
    long long nst = hassp ? (long long)((Ms + 2) / 2) * GRP : 0;   // sp thread count
    long long idx = (long long)blockIdx.x * blockDim.x + threadIdx.x;
    long long work = nbt + nst;
    if (idx < work) {
        int did, sid; const int* nbr; long long rel; int Mrows;
        if (idx < nbt) { did = bd; sid = bs; nbr = nbr_b; rel = idx;       Mrows = Mb + 1; }
        else           { did = sd; sid = ss; nbr = nbr_s; rel = idx - nbt; Mrows = Ms + 1; }
        int half = (Mrows + 1) / 2;
        int rr = (int)(rel / GRP);
        int g  = (int)(rel % GRP);
        int r0 = rr;
        int r1 = rr + half;
        bool doB = (r1 < Mrows);
        float4*       dst = valptr4(did);
        const float4* src = valptr4(sid);

        int2 nA = make_int2(0, 0), nB = make_int2(0, 0);
        if (r0 > 0) nA = ((const int2*)nbr)[r0 - 1];
        if (doB)    nB = ((const int2*)nbr)[r1 - 1];

        float4 a0, b0, c0, a1, b1, c1;
        if (r0 > 0) {
            a0 = src[(long long)r0   * GRP + g];
            b0 = src[(long long)nA.x * GRP + g];
            c0 = src[(long long)nA.y * GRP + g];
        }
        if (doB) {
            a1 = src[(long long)r1   * GRP + g];
            b1 = src[(long long)nB.x * GRP + g];
            c1 = src[(long long)nB.y * GRP + g];
        }
        if (r0 == 0) {
            dst[g] = make_float4(0.f, 0.f, 0.f, 0.f);
        } else {
            float4 o;
            o.x = a0.x + 0.5f * (b0.x + c0.x);
            o.y = a0.y + 0.5f * (b0.y + c0.y);
            o.z = a0.z + 0.5f * (b0.z + c0.z);
            o.w = a0.w + 0.5f * (b0.w + c0.w);
            dst[(long long)r0 * GRP + g] = o;
        }
        if (doB) {
            float4 o;
            o.x = a1.x + 0.5f * (b1.x + c1.x);
            o.y = a1.y + 0.5f * (b1.y + c1.y);
            o.z = a1.z + 0.5f * (b1.z + c1.z);
            o.w = a1.w + 0.5f * (b1.w + c1.w);
            dst[(long long)r1 * GRP + g] = o;
        }
        return;
    }
    long long z = idx - work;
    if (z < zna)            valptr4(za)[z]       = make_float4(0.f, 0.f, 0.f, 0.f);
    else if (z < zna + znb) valptr4(zb)[z - zna] = make_float4(0.f, 0.f, 0.f, 0.f);
}

// ---- fused slice(bi)+slice(sp)+softmax+Q (+splat of new Q into next buffers) ----
__global__ __launch_bounds__(256) void k_update_splat(
        const float* __restrict__ u, float* __restrict__ extout,
        const float* __restrict__ ws_bi, const int* __restrict__ os_bi,
        const float* __restrict__ ws_sp, const int* __restrict__ os_sp,
        int N, int usepair, int to_ext, int do_splat,
        int rd_bi, int rd_sp, int wr_bi, int wr_sp, float cb, float cs) {
    int tid = blockIdx.x * blockDim.x + threadIdx.x;
    int n = tid >> 3;
    int g = tid & 7;
    if (n >= N) return;

    float nb = g_nbi[n];
    float ns = g_nsp[n];
    float wbj[6]; int obj[6];
    float wsj[3]; int osj[3];
#pragma unroll
    for (int j = 0; j < 6; j++) { wbj[j] = ws_bi[n * 6 + j]; obj[j] = os_bi[n * 6 + j]; }
#pragma unroll
    for (int j = 0; j < 3; j++) { wsj[j] = ws_sp[n * 3 + j]; osj[j] = os_sp[n * 3 + j]; }

    float l0 = -1e30f, l1 = -1e30f, l2 = -1e30f, l3 = -1e30f;
    if (g < GRP) {
        float4 acc = make_float4(0.f, 0.f, 0.f, 0.f);
        if (usepair) {
            const float4* vb = valptr4(rd_bi);
            float pb = cb * nb;
#pragma unroll
            for (int j = 0; j < 6; j++) {
                float w = wbj[j] * pb;
                float4 v = vb[(long long)obj[j] * GRP + g];
                acc.x += w * v.x; acc.y += w * v.y; acc.z += w * v.z; acc.w += w * v.w;
            }
            const float4* vs = valptr4(rd_sp);
            float ps = cs * ns;
#pragma unroll
            for (int j = 0; j < 3; j++) {
                float w = wsj[j] * ps;
                float4 v = vs[(long long)osj[j] * GRP + g];
                acc.x += w * v.x; acc.y += w * v.y; acc.z += w * v.z; acc.w += w * v.w;
            }
        }
        long long ub = (long long)n * CC + g * 4;
        int c0 = g * 4;
        l0 = (c0 + 0 < CC) ? (acc.x - u[ub + 0]) : -1e30f;
        l1 = (c0 + 1 < CC) ? (acc.y - u[ub + 1]) : -1e30f;
        l2 = (c0 + 2 < CC) ? (acc.z - u[ub + 2]) : -1e30f;
        l3 = (c0 + 3 < CC) ? (acc.w - u[ub + 3]) : -1e30f;
    }

    float mx = fmaxf(fmaxf(l0, l1), fmaxf(l2, l3));
#pragma unroll
    for (int d = 1; d < 8; d <<= 1)
        mx = fmaxf(mx, __shfl_xor_sync(0xffffffffu, mx, d, 8));
    float e0 = expf(l0 - mx), e1 = expf(l1 - mx), e2 = expf(l2 - mx), e3 = expf(l3 - mx);
    float s = e0 + e1 + e2 + e3;
#pragma unroll
    for (int d = 1; d < 8; d <<= 1)
        s += __shfl_xor_sync(0xffffffffu, s, d, 8);
    float inv = 1.0f / s;

    if (g < GRP) {
        float4 q = make_float4(e0 * inv, e1 * inv, e2 * inv, e3 * inv);
        if (to_ext) {
            long long ob = (long long)n * CC + g * 4;
            int c0 = g * 4;
            if (c0 + 0 < CC) extout[ob + 0] = q.x;
            if (c0 + 1 < CC) extout[ob + 1] = q.y;
            if (c0 + 2 < CC) extout[ob + 2] = q.z;
            if (c0 + 3 < CC) extout[ob + 3] = q.w;
        }
        if (do_splat) {
            float4* vb = valptr4(wr_bi);
#pragma unroll
            for (int j = 0; j < 6; j++) {
                float w = wbj[j] * nb;
                red_add_v4(vb + (long long)obj[j] * GRP + g,
                           w * q.x, w * q.y, w * q.z, w * q.w);
            }
            float4* vs = valptr4(wr_sp);
#pragma unroll
            for (int j = 0; j < 3; j++) {
                float w = wsj[j] * ns;
                red_add_v4(vs + (long long)osj[j] * GRP + g,
                           w * q.x, w * q.y, w * q.z, w * q.w);
            }
        }
    }
}

// ---------------------------------------------------------------------------

static inline unsigned gridFor(long long n) { return (unsigned)((n + 255) / 256); }

extern "C" void kernel_launch(void* const* d_in, const int* in_sizes, int n_in,
                              void* d_out, int out_size) {
    const float* unary  = (const float*)d_in[0];
    const float* ws_bi  = (const float*)d_in[1];
    const float* ws_sp  = (const float*)d_in[2];
    const int*   os_bi  = (const int*)  d_in[3];
    const int*   os_sp  = (const int*)  d_in[4];
    const int*   nbr_bi = (const int*)  d_in[5];
    const int*   nbr_sp = (const int*)  d_in[6];
    float*       out    = (float*)d_out;

    const int N   = in_sizes[1] / 6;
    const int Mbi = in_sizes[5] / 12;
    const int Msp = in_sizes[6] / 6;
    const float ALPHA_BI = 32.0f / 33.0f;  // 1/(1+2^-5)
    const float ALPHA_SP = 0.8f;           // 1/(1+2^-2)
    const float CB = 10.0f * ALPHA_BI;
    const float CS = 3.0f  * ALPHA_SP;
    const int B = 256;

    const long long NB4 = (long long)(Mbi + 1) * GRP;   // full bi buffer in float4s
    const long long NS4 = (long long)(Msp + 1) * GRP;
    const long long BT  = (long long)((Mbi + 2) / 2) * GRP;  // blur thread counts
    const long long ST  = (long long)((Msp + 2) / 2) * GRP;

    // ---- prologue: normalization constants ----
    // norm chain uses fronts of bi0/bi1 and sp3/sp4; initial splat targets bi2/sp5.
    k_zero_fronts<<<gridFor((Mbi + 1) + (Msp + 1)), B>>>(0, Mbi + 1, 3, Msp + 1);
    k_splat1z<<<gridFor((long long)N * 9 + NB4 + NS4), B>>>(
        ws_bi, os_bi, N * 6, ws_sp, os_sp, N * 3, 2, NB4, 5, NS4);
    {
        int cb_ = 0, cs_ = 3;
        for (int j = 0; j < 6; j++) {
            int hassp = (j < 3);
            int bd = 1 - cb_;
            int sd = (cs_ == 3) ? 4 : 3;
            long long tot = (Mbi + 1) + (hassp ? (Msp + 1) : 0);
            k_blur1_both<<<gridFor(tot), B>>>(bd, cb_, nbr_bi + (long long)j * Mbi * 2, Mbi,
                                              sd, cs_, nbr_sp + (long long)j * Msp * 2, Msp, hassp);
            cb_ = bd;
            if (hassp) cs_ = sd;
        }
        // bi final in 0, sp final in 4
        k_norm_both<<<gridFor(N), B>>>(cb_, cs_, ws_bi, os_bi, ws_sp, os_sp, N, ALPHA_BI, ALPHA_SP);
    }

    // ---- initial Q = softmax(-u), splat into bi2 / sp5 ----
    k_update_splat<<<gridFor((long long)N * 8), B>>>(
        unary, out, ws_bi, os_bi, ws_sp, os_sp, N,
        /*usepair=*/0, /*to_ext=*/0, /*do_splat=*/1,
        0, 3, /*wr_bi=*/2, /*wr_sp=*/5, CB, CS);

    // ---- mean-field iterations (triple-buffer rotation) ----
    int sB = 2, tB = 0, zB = 1;   // bi: splat-src / pong / to-zero
    int sS = 5, tS = 3, zS = 4;   // sp
    for (int it = 0; it < 5; it++) {
        int c = sB, csp = sS;
        for (int j = 0; j < 6; j++) {
            int hassp = (j < 3);
            int d   = (c == sB) ? tB : sB;
            int dsp = (csp == sS) ? tS : sS;
            long long tot = BT + (hassp ? ST : 0) + ((j == 0) ? (NB4 + NS4) : 0);
            if (j == 0) {
                k_blur4z<<<gridFor(tot), B>>>(d, c, nbr_bi + (long long)j * Mbi * 2, Mbi,
                                              dsp, csp, nbr_sp + (long long)j * Msp * 2, Msp,
                                              hassp, zB, NB4, zS, NS4);
            } else {
                k_blur4z<<<gridFor(tot), B>>>(d, c, nbr_bi + (long long)j * Mbi * 2, Mbi,
                                              dsp, csp, nbr_sp + (long long)j * Msp * 2, Msp,
                                              hassp, 0, 0, 0, 0);
            }
            c = d;
            if (hassp) csp = dsp;
        }
        // bi blurred result in sB (6 flips), sp in tS (3 flips)
        if (it < 4) {
            k_update_splat<<<gridFor((long long)N * 8), B>>>(
                unary, out, ws_bi, os_bi, ws_sp, os_sp, N,
                /*usepair=*/1, /*to_ext=*/0, /*do_splat=*/1,
                sB, tS, /*wr_bi=*/zB, /*wr_sp=*/zS, CB, CS);
            // rotate: new splat buffer becomes source; old source gets zeroed next.
            int nB_ = zB; zB = sB; sB = nB_;                 // tB unchanged
            int nS_ = zS; zS = tS; tS = sS; sS = nS_;
        } else {
            k_update_splat<<<gridFor((long long)N * 8), B>>>(
                unary, out, ws_bi, os_bi, ws_sp, os_sp, N,
                /*usepair=*/1, /*to_ext=*/1, /*do_splat=*/0,
                sB, tS, 0, 3, CB, CS);
        }
    }
}

// round 7
// speedup vs baseline: 1.6940x; 1.6940x over previous
#include <cuda_runtime.h>
#include <cuda_fp16.h>
#include <math.h>

// ---------------------------------------------------------------------------
// DenseCRF mean-field with permutohedral lattice filtering.
// 21-ch lattice buffers stored as fp16 (24 padded ch = 48B rows = 3 uint4),
// fp32 compute, fp32 1-channel normalization chain, fused update+splat,
// merged bi/sp launches, triple-buffered with zero riding in blur pass 0.
// ---------------------------------------------------------------------------

#define CC 21
#define GRPH 3                      // uint4 groups per fp16 row (8 halves each)
static constexpr int       NPIX    = 512 * 512;
static constexpr long long ROWS_BI = 6LL * NPIX + 1;
static constexpr long long ROWS_SP = 3LL * NPIX + 1;

// fp16 value buffers (uint4 = 8 halves)
__device__ uint4 g_hb0[ROWS_BI * GRPH];
__device__ uint4 g_hb1[ROWS_BI * GRPH];
__device__ uint4 g_hb2[ROWS_BI * GRPH];
__device__ uint4 g_hs0[ROWS_SP * GRPH];
__device__ uint4 g_hs1[ROWS_SP * GRPH];
__device__ uint4 g_hs2[ROWS_SP * GRPH];
// fp32 1-channel norm-chain scratch
__device__ float g_v1a[ROWS_BI], g_v1b[ROWS_BI];
__device__ float g_w1a[ROWS_SP], g_w1b[ROWS_SP];
// per-pixel norms
__device__ float g_nbi[NPIX];
__device__ float g_nsp[NPIX];

__device__ __forceinline__ uint4* hbi(int i) { return i == 0 ? g_hb0 : (i == 1 ? g_hb1 : g_hb2); }
__device__ __forceinline__ uint4* hsp(int i) { return i == 0 ? g_hs0 : (i == 1 ? g_hs1 : g_hs2); }
__device__ __forceinline__ float* n1bi(int i) { return i ? g_v1b : g_v1a; }
__device__ __forceinline__ float* n1sp(int i) { return i ? g_w1b : g_w1a; }

__device__ __forceinline__ unsigned pack2(float a, float b) {
    __half2 h = __floats2half2_rn(a, b);
    return *reinterpret_cast<unsigned*>(&h);
}
__device__ __forceinline__ float2 unp2(unsigned u) {
    __half2 h = *reinterpret_cast<__half2*>(&u);
    return __half22float2(h);
}
__device__ __forceinline__ unsigned comb2(unsigned a, unsigned b, unsigned c) {
    float2 fa = unp2(a), fb = unp2(b), fc = unp2(c);
    return pack2(fa.x + 0.5f * (fb.x + fc.x), fa.y + 0.5f * (fb.y + fc.y));
}
__device__ __forceinline__ void red4h(uint4* p, unsigned a, unsigned b, unsigned c, unsigned d) {
    asm volatile("red.global.add.noftz.v4.f16x2 [%0], {%1, %2, %3, %4};"
                 :: "l"(p), "r"(a), "r"(b), "r"(c), "r"(d) : "memory");
}

// ---------------------------------------------------------------------------

__global__ __launch_bounds__(256) void k_zero_fronts(long long na, long long nb) {
    long long i = (long long)blockIdx.x * blockDim.x + threadIdx.x;
    if (i >= na + nb) return;
    if (i < na) g_v1a[i]      = 0.0f;
    else        g_w1a[i - na] = 0.0f;
}

// 1-ch splat for both lattices + zero two fp16 buffers (uint4 counts)
__global__ __launch_bounds__(256) void k_splat1z(const float* __restrict__ ws_bi,
                                                 const int* __restrict__ os_bi, int N6,
                                                 const float* __restrict__ ws_sp,
                                                 const int* __restrict__ os_sp, int N3,
                                                 int zbi, long long zna,
                                                 int zsp, long long znb) {
    long long i = (long long)blockIdx.x * blockDim.x + threadIdx.x;
    if (i < N6) { atomicAdd(g_v1a + os_bi[i], ws_bi[i]); return; }
    if (i < N6 + N3) { long long j = i - N6; atomicAdd(g_w1a + os_sp[j], ws_sp[j]); return; }
    long long z = i - (N6 + N3);
    uint4 zz = make_uint4(0, 0, 0, 0);
    if (z < zna)            hbi(zbi)[z]       = zz;
    else if (z < zna + znb) hsp(zsp)[z - zna] = zz;
}

__global__ __launch_bounds__(256) void k_blur1_both(int bd, int bs,
                                                    const int* __restrict__ nbr_b, int Mb,
                                                    int sd, int ss,
                                                    const int* __restrict__ nbr_s, int Ms,
                                                    int hassp) {
    int nb = Mb + 1;
    int ns = hassp ? (Ms + 1) : 0;
    int i = blockIdx.x * blockDim.x + threadIdx.x;
    if (i >= nb + ns) return;
    float* dst; const float* src; const int* nbr; int r;
    if (i < nb) { dst = n1bi(bd); src = n1bi(bs); nbr = nbr_b; r = i; }
    else        { dst = n1sp(sd); src = n1sp(ss); nbr = nbr_s; r = i - nb; }
    if (r == 0) { dst[0] = 0.0f; return; }
    int2 nn = ((const int2*)nbr)[r - 1];
    dst[r] = src[r] + 0.5f * (src[nn.x] + src[nn.y]);
}

__global__ __launch_bounds__(256) void k_norm_both(int bvid, int svid,
                                                   const float* __restrict__ ws_bi,
                                                   const int* __restrict__ os_bi,
                                                   const float* __restrict__ ws_sp,
                                                   const int* __restrict__ os_sp,
                                                   int N, float a_bi, float a_sp) {
    int n = blockIdx.x * blockDim.x + threadIdx.x;
    if (n >= N) return;
    const float* vb = n1bi(bvid);
    float s = 0.0f;
#pragma unroll
    for (int j = 0; j < 6; j++) s += ws_bi[n * 6 + j] * vb[os_bi[n * 6 + j]];
    g_nbi[n] = 1.0f / (sqrtf(a_bi * s) + 1e-20f);
    const float* vs = n1sp(svid);
    float t = 0.0f;
#pragma unroll
    for (int j = 0; j < 3; j++) t += ws_sp[n * 3 + j] * vs[os_sp[n * 3 + j]];
    g_nsp[n] = 1.0f / (sqrtf(a_sp * t) + 1e-20f);
}

// ---- fp16 24-ch blur, bi+sp merged, optional zero tail ----
__global__ __launch_bounds__(256) void k_blurHz(int bd, int bs,
                                                const int* __restrict__ nbr_b, int Mb,
                                                int sd, int ss,
                                                const int* __restrict__ nbr_s, int Ms,
                                                int hassp,
                                                int zbi, long long zna,
                                                int zsp, long long znb) {
    long long nbt = (long long)(Mb + 1) * GRPH;
    long long nst = hassp ? (long long)(Ms + 1) * GRPH : 0;
    long long idx = (long long)blockIdx.x * blockDim.x + threadIdx.x;
    if (idx < nbt + nst) {
        uint4* dst; const uint4* src; const int* nbr; long long rel;
        if (idx < nbt) { dst = hbi(bd); src = hbi(bs); nbr = nbr_b; rel = idx; }
        else           { dst = hsp(sd); src = hsp(ss); nbr = nbr_s; rel = idx - nbt; }
        int r = (int)(rel / GRPH);
        int g = (int)(rel % GRPH);
        if (r == 0) { dst[g] = make_uint4(0, 0, 0, 0); return; }
        int2 nn = ((const int2*)nbr)[r - 1];
        uint4 a = src[rel];
        uint4 b = src[(long long)nn.x * GRPH + g];
        uint4 c = src[(long long)nn.y * GRPH + g];
        uint4 o;
        o.x = comb2(a.x, b.x, c.x);
        o.y = comb2(a.y, b.y, c.y);
        o.z = comb2(a.z, b.z, c.z);
        o.w = comb2(a.w, b.w, c.w);
        dst[rel] = o;
        return;
    }
    long long z = idx - (nbt + nst);
    uint4 zz = make_uint4(0, 0, 0, 0);
    if (z < zna)            hbi(zbi)[z]       = zz;
    else if (z < zna + znb) hsp(zsp)[z - zna] = zz;
}

// ---- fused slice(bi)+slice(sp)+softmax+Q (+splat into next fp16 buffers) ----
// 4 lanes per pixel; lanes 0..2 own 8 channels each (24 padded), lane 3 idle.
__global__ __launch_bounds__(256) void k_update_splat(
        const float* __restrict__ u, float* __restrict__ extout,
        const float* __restrict__ ws_bi, const int* __restrict__ os_bi,
        const float* __restrict__ ws_sp, const int* __restrict__ os_sp,
        int N, int usepair, int to_ext, int do_splat,
        int rd_bi, int rd_sp, int wr_bi, int wr_sp, float cb, float cs) {
    int tid = blockIdx.x * blockDim.x + threadIdx.x;
    int n = tid >> 2;
    int g = tid & 3;
    if (n >= N) return;
    bool act = (g < GRPH);

    float nb = g_nbi[n];
    float ns = g_nsp[n];
    float wbj[6]; int obj[6];
    float wsj[3]; int osj[3];
#pragma unroll
    for (int j = 0; j < 6; j++) { wbj[j] = ws_bi[n * 6 + j]; obj[j] = os_bi[n * 6 + j]; }
#pragma unroll
    for (int j = 0; j < 3; j++) { wsj[j] = ws_sp[n * 3 + j]; osj[j] = os_sp[n * 3 + j]; }

    float l[8];
#pragma unroll
    for (int k = 0; k < 8; k++) l[k] = -1e30f;

    if (act) {
        float acc[8];
#pragma unroll
        for (int k = 0; k < 8; k++) acc[k] = 0.0f;
        if (usepair) {
            const uint4* vb = hbi(rd_bi);
            float pb = cb * nb;
#pragma unroll
            for (int j = 0; j < 6; j++) {
                float w = wbj[j] * pb;
                uint4 v = vb[(long long)obj[j] * GRPH + g];
                float2 f0 = unp2(v.x), f1 = unp2(v.y), f2 = unp2(v.z), f3 = unp2(v.w);
                acc[0] += w * f0.x; acc[1] += w * f0.y;
                acc[2] += w * f1.x; acc[3] += w * f1.y;
                acc[4] += w * f2.x; acc[5] += w * f2.y;
                acc[6] += w * f3.x; acc[7] += w * f3.y;
            }
            const uint4* vs = hsp(rd_sp);
            float ps = cs * ns;
#pragma unroll
            for (int j = 0; j < 3; j++) {
                float w = wsj[j] * ps;
                uint4 v = vs[(long long)osj[j] * GRPH + g];
                float2 f0 = unp2(v.x), f1 = unp2(v.y), f2 = unp2(v.z), f3 = unp2(v.w);
                acc[0] += w * f0.x; acc[1] += w * f0.y;
                acc[2] += w * f1.x; acc[3] += w * f1.y;
                acc[4] += w * f2.x; acc[5] += w * f2.y;
                acc[6] += w * f3.x; acc[7] += w * f3.y;
            }
        }
        int c0 = g * 8;
        long long ub = (long long)n * CC + c0;
#pragma unroll
        for (int k = 0; k < 8; k++)
            if (c0 + k < CC) l[k] = acc[k] - u[ub + k];
    }

    // softmax across the 4-lane group (24 padded channels; pads -> exp = 0)
    float mx = l[0];
#pragma unroll
    for (int k = 1; k < 8; k++) mx = fmaxf(mx, l[k]);
#pragma unroll
    for (int d = 1; d < 4; d <<= 1)
        mx = fmaxf(mx, __shfl_xor_sync(0xffffffffu, mx, d, 4));
    float e[8], s = 0.0f;
#pragma unroll
    for (int k = 0; k < 8; k++) { e[k] = expf(l[k] - mx); s += e[k]; }
#pragma unroll
    for (int d = 1; d < 4; d <<= 1)
        s += __shfl_xor_sync(0xffffffffu, s, d, 4);
    float inv = 1.0f / s;

    if (act) {
        float q[8];
#pragma unroll
        for (int k = 0; k < 8; k++) q[k] = e[k] * inv;
        if (to_ext) {
            int c0 = g * 8;
            long long ob = (long long)n * CC + c0;
#pragma unroll
            for (int k = 0; k < 8; k++)
                if (c0 + k < CC) extout[ob + k] = q[k];
        }
        if (do_splat) {
            uint4* vb = hbi(wr_bi);
#pragma unroll
            for (int j = 0; j < 6; j++) {
                float w = wbj[j] * nb;
                red4h(vb + (long long)obj[j] * GRPH + g,
                      pack2(w * q[0], w * q[1]), pack2(w * q[2], w * q[3]),
                      pack2(w * q[4], w * q[5]), pack2(w * q[6], w * q[7]));
            }
            uint4* vs = hsp(wr_sp);
#pragma unroll
            for (int j = 0; j < 3; j++) {
                float w = wsj[j] * ns;
                red4h(vs + (long long)osj[j] * GRPH + g,
                      pack2(w * q[0], w * q[1]), pack2(w * q[2], w * q[3]),
                      pack2(w * q[4], w * q[5]), pack2(w * q[6], w * q[7]));
            }
        }
    }
}

// ---------------------------------------------------------------------------

static inline unsigned gridFor(long long n) { return (unsigned)((n + 255) / 256); }

extern "C" void kernel_launch(void* const* d_in, const int* in_sizes, int n_in,
                              void* d_out, int out_size) {
    const float* unary  = (const float*)d_in[0];
    const float* ws_bi  = (const float*)d_in[1];
    const float* ws_sp  = (const float*)d_in[2];
    const int*   os_bi  = (const int*)  d_in[3];
    const int*   os_sp  = (const int*)  d_in[4];
    const int*   nbr_bi = (const int*)  d_in[5];
    const int*   nbr_sp = (const int*)  d_in[6];
    float*       out    = (float*)d_out;

    const int N   = in_sizes[1] / 6;
    const int Mbi = in_sizes[5] / 12;
    const int Msp = in_sizes[6] / 6;
    const float ALPHA_BI = 32.0f / 33.0f;  // 1/(1+2^-5)
    const float ALPHA_SP = 0.8f;           // 1/(1+2^-2)
    const float CB = 10.0f * ALPHA_BI;
    const float CS = 3.0f  * ALPHA_SP;
    const int B = 256;

    const long long NBH = (long long)(Mbi + 1) * GRPH;   // fp16 buffer in uint4s
    const long long NSH = (long long)(Msp + 1) * GRPH;

    // ---- prologue: normalization constants (fp32 1-channel chain) ----
    k_zero_fronts<<<gridFor((Mbi + 1) + (Msp + 1)), B>>>(Mbi + 1, Msp + 1);
    k_splat1z<<<gridFor((long long)N * 9 + NBH + NSH), B>>>(
        ws_bi, os_bi, N * 6, ws_sp, os_sp, N * 3, 2, NBH, 2, NSH);
    {
        int cb_ = 0, cs_ = 0;
        for (int j = 0; j < 6; j++) {
            int hassp = (j < 3);
            int bd = 1 - cb_;
            int sd = 1 - cs_;
            long long tot = (Mbi + 1) + (hassp ? (Msp + 1) : 0);
            k_blur1_both<<<gridFor(tot), B>>>(bd, cb_, nbr_bi + (long long)j * Mbi * 2, Mbi,
                                              sd, cs_, nbr_sp + (long long)j * Msp * 2, Msp, hassp);
            cb_ = bd;
            if (hassp) cs_ = sd;
        }
        // bi final in 0 (6 flips), sp final in 1 (3 flips)
        k_norm_both<<<gridFor(N), B>>>(cb_, cs_, ws_bi, os_bi, ws_sp, os_sp, N, ALPHA_BI, ALPHA_SP);
    }

    // ---- initial Q = softmax(-u), splat into bi2 / sp2 (zeroed in k_splat1z) ----
    k_update_splat<<<gridFor((long long)N * 4), B>>>(
        unary, out, ws_bi, os_bi, ws_sp, os_sp, N,
        /*usepair=*/0, /*to_ext=*/0, /*do_splat=*/1,
        0, 0, /*wr_bi=*/2, /*wr_sp=*/2, CB, CS);

    // ---- mean-field iterations (triple-buffer rotation) ----
    int sB = 2, tB = 0, zB = 1;   // bi: splat-src / pong / to-zero
    int sS = 2, tS = 0, zS = 1;   // sp
    for (int it = 0; it < 5; it++) {
        int c = sB, csp = sS;
        for (int j = 0; j < 6; j++) {
            int hassp = (j < 3);
            int d   = (c   == sB) ? tB : sB;
            int dsp = (csp == sS) ? tS : sS;
            long long tot = NBH + (hassp ? NSH : 0) + ((j == 0) ? (NBH + NSH) : 0);
            if (j == 0) {
                k_blurHz<<<gridFor(tot), B>>>(d, c, nbr_bi + (long long)j * Mbi * 2, Mbi,
                                              dsp, csp, nbr_sp + (long long)j * Msp * 2, Msp,
                                              hassp, zB, NBH, zS, NSH);
            } else {
                k_blurHz<<<gridFor(tot), B>>>(d, c, nbr_bi + (long long)j * Mbi * 2, Mbi,
                                              dsp, csp, nbr_sp + (long long)j * Msp * 2, Msp,
                                              hassp, 0, 0, 0, 0);
            }
            c = d;
            if (hassp) csp = dsp;
        }
        // bi result in sB (6 flips), sp result in tS (3 flips)
        if (it < 4) {
            k_update_splat<<<gridFor((long long)N * 4), B>>>(
                unary, out, ws_bi, os_bi, ws_sp, os_sp, N,
                /*usepair=*/1, /*to_ext=*/0, /*do_splat=*/1,
                sB, tS, /*wr_bi=*/zB, /*wr_sp=*/zS, CB, CS);
            int nB_ = zB; zB = sB; sB = nB_;                   // tB unchanged
            int nS_ = zS; zS = tS; tS = sS; sS = nS_;
        } else {
            k_update_splat<<<gridFor((long long)N * 4), B>>>(
                unary, out, ws_bi, os_bi, ws_sp, os_sp, N,
                /*usepair=*/1, /*to_ext=*/1, /*do_splat=*/0,
                sB, tS, 0, 0, CB, CS);
        }
    }
}